// round 2
// baseline (speedup 1.0000x reference)
#include <cuda_runtime.h>
#include <math.h>

// ---------------------------------------------------------------------------
// FCOS post-processing: decode + class-aware greedy NMS (exact, sort-free)
// ---------------------------------------------------------------------------

#define BATCH    16
#define NCLS     80
#define NTOT     17064            // 12800 + 3200 + 800 + 208 + 56
#define NTHREADS 1024
#define CHUNK    17               // 1024 * 17 = 17408 >= 17064
#define NPAD     (NTHREADS * CHUNK)
#define POSTK    100

__device__ float         g_score[BATCH * NTOT];
__device__ float4        g_box  [BATCH * NTOT];
__device__ unsigned char g_cls  [BATCH * NTOT];

struct LevelPtrs {
    const float* cls[5];
    const float* box[5];
    const float* ctr[5];
};

__constant__ int   c_off[6]    = {0, 12800, 16000, 16800, 17008, 17064};
__constant__ int   c_W[5]      = {128, 64, 32, 16, 8};
__constant__ float c_stride[5] = {8.f, 16.f, 32.f, 64.f, 128.f};

__device__ __forceinline__ float sigmoidf_(float x) {
    return 1.0f / (1.0f + expf(-x));
}

// ---------------------------------------------------------------------------
// Kernel 1: decode.  One thread per (batch, anchor).
// ---------------------------------------------------------------------------
__global__ void decode_kernel(LevelPtrs p) {
    int a = blockIdx.x * blockDim.x + threadIdx.x;
    int b = blockIdx.y;
    if (a >= NTOT) return;

    int lvl = 0;
    while (a >= c_off[lvl + 1]) lvl++;
    int   hw     = a - c_off[lvl];
    int   W      = c_W[lvl];
    int   HW     = (c_off[lvl + 1] - c_off[lvl]);
    float stride = c_stride[lvl];

    // argmax over 80 class logits (coalesced: consecutive threads = consecutive hw)
    const float* cp = p.cls[lvl] + (size_t)(b * NCLS) * HW + hw;
    float best = cp[0];
    int   bi   = 0;
#pragma unroll 8
    for (int c = 1; c < NCLS; c++) {
        float v = cp[(size_t)c * HW];
        if (v > best) { best = v; bi = c; }
    }

    float ctr   = p.ctr[lvl][(size_t)b * HW + hw];
    float score = sqrtf(sigmoidf_(best) * sigmoidf_(ctr));

    const float* bp = p.box[lvl] + (size_t)(b * 4) * HW + hw;
    float l = bp[0]      * stride;
    float t = bp[HW]     * stride;
    float r = bp[2 * HW] * stride;
    float d = bp[3 * HW] * stride;

    int   w  = hw % W;
    int   h  = hw / W;
    float px = w * stride + stride * 0.5f;
    float py = h * stride + stride * 0.5f;

    float x1 = fminf(fmaxf(px - l, 0.f), 1023.f);  // IMG_W - 1
    float y1 = fminf(fmaxf(py - t, 0.f), 799.f);   // IMG_H - 1
    float x2 = fminf(fmaxf(px + r, 0.f), 1023.f);
    float y2 = fminf(fmaxf(py + d, 0.f), 799.f);

    int gi = b * NTOT + a;
    g_score[gi] = score;
    g_cls[gi]   = (unsigned char)bi;
    g_box[gi]   = make_float4(x1, y1, x2, y2);
}

// ---------------------------------------------------------------------------
// Kernel 2: class-aware greedy NMS, one block per batch element.
// Iterative argmax (exactly equivalent to reference's scan since the per-level
// sorts only permute candidates). Class offset trick == "same class only".
// ---------------------------------------------------------------------------
__global__ void __launch_bounds__(NTHREADS, 1) nms_kernel(float* __restrict__ out) {
    extern __shared__ char smem[];
    float*         s_score = (float*)smem;                       // NPAD floats
    unsigned char* s_cls   = (unsigned char*)(smem + NPAD * 4);  // NPAD bytes

    __shared__ float s_rv[32];
    __shared__ int   s_ri[32];
    __shared__ float s_pbox[4];
    __shared__ int   s_pcls;
    __shared__ float s_pval;
    __shared__ int   s_pidx;

    const int   b   = blockIdx.x;
    const int   tid = threadIdx.x;
    const float NEG = -INFINITY;

    // Coalesced load of scores + classes into smem
    for (int i = tid; i < NPAD; i += NTHREADS) {
        if (i < NTOT) {
            s_score[i] = g_score[b * NTOT + i];
            s_cls[i]   = g_cls[b * NTOT + i];
        } else {
            s_score[i] = NEG;
            s_cls[i]   = 255;
        }
    }
    __syncthreads();

    // Per-thread chunk max in registers
    const int base = tid * CHUNK;
    float lmax = NEG;
    int   lidx = base;
#pragma unroll
    for (int j = 0; j < CHUNK; j++) {
        float v = s_score[base + j];
        if (v > lmax) { lmax = v; lidx = base + j; }
    }

    int kept = POSTK;
    for (int k = 0; k < POSTK; k++) {
        // -------- global argmax: warp shuffle reduce, then warp0 reduce ----
        float v   = lmax;
        int   idx = lidx;
#pragma unroll
        for (int off = 16; off; off >>= 1) {
            float ov = __shfl_down_sync(0xffffffffu, v, off);
            int   oi = __shfl_down_sync(0xffffffffu, idx, off);
            if (ov > v || (ov == v && oi < idx)) { v = ov; idx = oi; }
        }
        if ((tid & 31) == 0) { s_rv[tid >> 5] = v; s_ri[tid >> 5] = idx; }
        __syncthreads();
        if (tid < 32) {
            v   = s_rv[tid];
            idx = s_ri[tid];
#pragma unroll
            for (int off = 16; off; off >>= 1) {
                float ov = __shfl_down_sync(0xffffffffu, v, off);
                int   oi = __shfl_down_sync(0xffffffffu, idx, off);
                if (ov > v || (ov == v && oi < idx)) { v = ov; idx = oi; }
            }
            if (tid == 0) {
                s_pval = v;
                s_pidx = idx;
                if (v != NEG) {
                    float4 pb = g_box[b * NTOT + idx];
                    s_pbox[0] = pb.x; s_pbox[1] = pb.y;
                    s_pbox[2] = pb.z; s_pbox[3] = pb.w;
                    int pc = s_cls[idx];
                    s_pcls = pc;
                    // write detection row: [x1,y1,x2,y2,score]
                    float* det = out + ((size_t)b * POSTK + k) * 5;
                    det[0] = pb.x; det[1] = pb.y; det[2] = pb.z; det[3] = pb.w;
                    det[4] = v;
                    out[(size_t)BATCH * POSTK * 5 + b * POSTK + k] = (float)pc;
                }
            }
        }
        __syncthreads();

        float pv = s_pval;
        if (pv == NEG) { kept = k; break; }

        const int   pidx = s_pidx;
        const int   pcls = s_pcls;
        const float px1 = s_pbox[0], py1 = s_pbox[1];
        const float px2 = s_pbox[2], py2 = s_pbox[3];
        const float pa  = (px2 - px1) * (py2 - py1);

        // -------- suppression over own chunk (same-class live entries) -----
        bool dirty = false;
#pragma unroll
        for (int j = 0; j < CHUNK; j++) {
            int   i  = base + j;
            float sc = s_score[i];
            if (sc != NEG && s_cls[i] == pcls) {
                float4 bb   = g_box[b * NTOT + i];
                float ix1   = fmaxf(px1, bb.x), iy1 = fmaxf(py1, bb.y);
                float ix2   = fminf(px2, bb.z), iy2 = fminf(py2, bb.w);
                float inter = fmaxf(ix2 - ix1, 0.f) * fmaxf(iy2 - iy1, 0.f);
                float ar    = (bb.z - bb.x) * (bb.w - bb.y);
                float iou   = inter / (pa + ar - inter + 1e-9f);
                if (iou > 0.6f) { s_score[i] = NEG; dirty = true; }
            }
        }
        // explicit self-removal (zero-area picked boxes have self-IoU 0)
        if (pidx >= base && pidx < base + CHUNK) { s_score[pidx] = NEG; dirty = true; }

        if (dirty) {
            lmax = NEG; lidx = base;
#pragma unroll
            for (int j = 0; j < CHUNK; j++) {
                float vv = s_score[base + j];
                if (vv > lmax) { lmax = vv; lidx = base + j; }
            }
        }
        // next iteration's first __syncthreads orders suppression vs. s_p* reuse
    }

    // fill remaining slots with defaults (box=0, score=-1, class=-1)
    for (int k2 = kept + tid; k2 < POSTK; k2 += NTHREADS) {
        float* det = out + ((size_t)b * POSTK + k2) * 5;
        det[0] = 0.f; det[1] = 0.f; det[2] = 0.f; det[3] = 0.f; det[4] = -1.f;
        out[(size_t)BATCH * POSTK * 5 + b * POSTK + k2] = -1.f;
    }
}

// ---------------------------------------------------------------------------
// Launch.  Input order detected at runtime from in_sizes:
//   planar      (signature order): cls x5, box x5, ctr x5  -> in_sizes[1] = 4096000
//   interleaved (dict order):      (cls,box,ctr) per level -> in_sizes[1] = 819200
// ---------------------------------------------------------------------------
extern "C" void kernel_launch(void* const* d_in, const int* in_sizes, int n_in,
                              void* d_out, int out_size) {
    (void)n_in; (void)out_size;

    LevelPtrs p;
    if (in_sizes[1] == 819200) {
        // interleaved: d_in[3*i + {0,1,2}] = cls, box, ctr of level i
        for (int i = 0; i < 5; i++) {
            p.cls[i] = (const float*)d_in[3 * i + 0];
            p.box[i] = (const float*)d_in[3 * i + 1];
            p.ctr[i] = (const float*)d_in[3 * i + 2];
        }
    } else {
        // planar: cls x5, box x5, ctr x5
        for (int i = 0; i < 5; i++) {
            p.cls[i] = (const float*)d_in[i];
            p.box[i] = (const float*)d_in[5 + i];
            p.ctr[i] = (const float*)d_in[10 + i];
        }
    }

    // Non-stream API: executes immediately (also during graph capture, where it
    // is not recorded). Deterministic, no static guards.
    cudaFuncSetAttribute(nms_kernel,
                         cudaFuncAttributeMaxDynamicSharedMemorySize,
                         NPAD * 5);

    dim3 dgrid((NTOT + 255) / 256, BATCH);
    decode_kernel<<<dgrid, 256>>>(p);

    nms_kernel<<<BATCH, NTHREADS, NPAD * 5>>>((float*)d_out);
}

// round 3
// speedup vs baseline: 1.1138x; 1.1138x over previous
#include <cuda_runtime.h>
#include <math.h>

// ---------------------------------------------------------------------------
// FCOS post-processing, class-decomposed exact NMS.
//   Suppression is intra-class only (CLASS_OFFSET trick), so global greedy NMS
//   == union of per-(batch,class) greedy NMS survivors, output = top-100
//   survivors by descending score.
// ---------------------------------------------------------------------------

#define BATCH   16
#define NCLS    80
#define NTOT    17064          // 12800 + 3200 + 800 + 208 + 56
#define NGROUP  (NTOT / 4)     // 4266 (all level boundaries divisible by 4)
#define POSTK   100
#define NBUCKET (BATCH * NCLS) // 1280
#define CAP     768            // per-bucket smem capacity (expected ~213)
#define CANDCAP 2048

__device__ float         g_score[BATCH * NTOT];
__device__ float4        g_box  [BATCH * NTOT];
__device__ int           g_clspos[BATCH * NTOT];   // (pos<<8)|cls
__device__ int           d_cnt  [NBUCKET];
__device__ int           d_off  [NBUCKET];         // global base into d_items
__device__ unsigned short d_items[BATCH * NTOT];   // anchor idx within batch

struct LevelPtrs {
    const float* cls[5];
    const float* box[5];
    const float* ctr[5];
};

__constant__ int   c_off[6]    = {0, 12800, 16000, 16800, 17008, 17064};
__constant__ int   c_W[5]      = {128, 64, 32, 16, 8};
__constant__ float c_stride[5] = {8.f, 16.f, 32.f, 64.f, 128.f};

__device__ __forceinline__ float sigmoidf_(float x) {
    return 1.0f / (1.0f + expf(-x));
}
__device__ __forceinline__ float iou_(const float4 a, const float4 b) {
    float ix1 = fmaxf(a.x, b.x), iy1 = fmaxf(a.y, b.y);
    float ix2 = fminf(a.z, b.z), iy2 = fminf(a.w, b.w);
    float inter = fmaxf(ix2 - ix1, 0.f) * fmaxf(iy2 - iy1, 0.f);
    float aa = (a.z - a.x) * (a.w - a.y);
    float ab = (b.z - b.x) * (b.w - b.y);
    return inter / (aa + ab - inter + 1e-9f);
}

// ---------------------------------------------------------------------------
__global__ void reset_kernel() {
    int i = blockIdx.x * blockDim.x + threadIdx.x;
    if (i < NBUCKET) d_cnt[i] = 0;
}

// ---------------------------------------------------------------------------
// Decode: one thread per 4 consecutive anchors (same level, same row).
// ---------------------------------------------------------------------------
__global__ void decode_kernel(LevelPtrs p) {
    int g = blockIdx.x * blockDim.x + threadIdx.x;
    int b = blockIdx.y;
    if (g >= NGROUP) return;
    int a0 = g * 4;

    int lvl = (a0 >= 12800) + (a0 >= 16000) + (a0 >= 16800) + (a0 >= 17008);
    int   hw0    = a0 - c_off[lvl];
    int   HW     = c_off[lvl + 1] - c_off[lvl];
    int   HW4    = HW >> 2;
    int   W      = c_W[lvl];
    float stride = c_stride[lvl];

    // class argmax over 80 logits, 4 anchors at a time (sigmoid monotone)
    const float4* cp = reinterpret_cast<const float4*>(
        p.cls[lvl] + (size_t)b * NCLS * HW + hw0);
    float4 best = cp[0];
    int4   bi   = make_int4(0, 0, 0, 0);
#pragma unroll 4
    for (int c = 1; c < NCLS; c++) {
        float4 v = cp[(size_t)c * HW4];
        if (v.x > best.x) { best.x = v.x; bi.x = c; }
        if (v.y > best.y) { best.y = v.y; bi.y = c; }
        if (v.z > best.z) { best.z = v.z; bi.z = c; }
        if (v.w > best.w) { best.w = v.w; bi.w = c; }
    }

    float4 ct = *reinterpret_cast<const float4*>(p.ctr[lvl] + (size_t)b * HW + hw0);

    const float* bp = p.box[lvl] + (size_t)b * 4 * HW + hw0;
    float4 l4 = *reinterpret_cast<const float4*>(bp);
    float4 t4 = *reinterpret_cast<const float4*>(bp + HW);
    float4 r4 = *reinterpret_cast<const float4*>(bp + 2 * HW);
    float4 d4 = *reinterpret_cast<const float4*>(bp + 3 * HW);

    int   w0 = hw0 % W;
    int   h  = hw0 / W;
    float py = h * stride + 0.5f * stride;

    float sc[4] = {best.x, best.y, best.z, best.w};
    float cc[4] = {ct.x, ct.y, ct.z, ct.w};
    int   ci[4] = {bi.x, bi.y, bi.z, bi.w};
    float ll[4] = {l4.x, l4.y, l4.z, l4.w};
    float tt[4] = {t4.x, t4.y, t4.z, t4.w};
    float rr[4] = {r4.x, r4.y, r4.z, r4.w};
    float dd[4] = {d4.x, d4.y, d4.z, d4.w};

    float4 s4;
    float* s4p = &s4.x;
#pragma unroll
    for (int j = 0; j < 4; j++) {
        float px = (w0 + j) * stride + 0.5f * stride;
        float l = ll[j] * stride, t = tt[j] * stride;
        float r = rr[j] * stride, d = dd[j] * stride;
        float x1 = fminf(fmaxf(px - l, 0.f), 1023.f);
        float y1 = fminf(fmaxf(py - t, 0.f), 799.f);
        float x2 = fminf(fmaxf(px + r, 0.f), 1023.f);
        float y2 = fminf(fmaxf(py + d, 0.f), 799.f);
        float score = sqrtf(sigmoidf_(sc[j]) * sigmoidf_(cc[j]));
        s4p[j] = score;

        int gi = b * NTOT + a0 + j;
        g_box[gi] = make_float4(x1, y1, x2, y2);
        int pos = atomicAdd(&d_cnt[b * NCLS + ci[j]], 1);
        g_clspos[gi] = (pos << 8) | ci[j];
    }
    reinterpret_cast<float4*>(g_score)[(b * NTOT + a0) >> 2] = s4;
}

// ---------------------------------------------------------------------------
// Scan: offsets per bucket. 1 block.
// ---------------------------------------------------------------------------
__global__ void scan_kernel() {
    __shared__ int s_cnt[NBUCKET];
    int tid = threadIdx.x;
    for (int i = tid; i < NBUCKET; i += blockDim.x) s_cnt[i] = d_cnt[i];
    __syncthreads();
    if (tid < BATCH) {
        int base = 0;
        for (int c = 0; c < NCLS; c++) {
            d_off[tid * NCLS + c] = tid * NTOT + base;
            base += s_cnt[tid * NCLS + c];
        }
    }
}

// ---------------------------------------------------------------------------
__global__ void scatter_kernel() {
    int i = blockIdx.x * blockDim.x + threadIdx.x;
    if (i >= BATCH * NTOT) return;
    int b = i / NTOT, a = i - b * NTOT;
    int v = g_clspos[i];
    int cls = v & 0xFF, pos = v >> 8;
    d_items[d_off[b * NCLS + cls] + pos] = (unsigned short)a;
}

// ---------------------------------------------------------------------------
// Per-bucket greedy NMS. One warp per (batch,class). Suppressed -> score=-1.
// Order: descending score, ties by ascending anchor index (matches argmax).
// ---------------------------------------------------------------------------
__global__ void __launch_bounds__(64) nms_bucket_kernel() {
    __shared__ float          s_sc[2][CAP];
    __shared__ float4         s_bx[2][CAP];
    __shared__ unsigned short s_idx[2][CAP];
    __shared__ unsigned short s_ord[2][CAP];
    __shared__ unsigned char  s_keep[2][CAP];

    int w    = threadIdx.x >> 5;
    int lane = threadIdx.x & 31;
    int bid  = blockIdx.x * 2 + w;
    if (bid >= NBUCKET) return;
    int b   = bid / NCLS;
    int n   = d_cnt[bid];
    int off = d_off[bid];
    if (n == 0) return;

    if (n <= CAP) {
        for (int i = lane; i < n; i += 32) {
            int idx = d_items[off + i];
            s_idx[w][i] = (unsigned short)idx;
            s_sc[w][i]  = g_score[b * NTOT + idx];
            s_bx[w][i]  = g_box[b * NTOT + idx];
        }
        __syncwarp();
        // rank sort (score desc, idx asc)
        for (int i = lane; i < n; i += 32) {
            float si = s_sc[w][i];
            int   ii = s_idx[w][i];
            int   r  = 0;
            for (int j = 0; j < n; j++) {
                float sj = s_sc[w][j];
                r += (sj > si) || (sj == si && s_idx[w][j] < ii);
            }
            s_ord[w][r]  = (unsigned short)i;
            s_keep[w][r] = 1;
        }
        __syncwarp();
        // greedy
        for (int r = 0; r < n; r++) {
            if (!s_keep[w][r]) continue;
            int    pp = s_ord[w][r];
            float4 pb = s_bx[w][pp];
            for (int r2 = r + 1 + lane; r2 < n; r2 += 32) {
                if (!s_keep[w][r2]) continue;
                float4 qb = s_bx[w][s_ord[w][r2]];
                if (iou_(pb, qb) > 0.6f) s_keep[w][r2] = 0;
            }
            __syncwarp();
        }
        for (int r = lane; r < n; r += 32) {
            if (!s_keep[w][r])
                g_score[b * NTOT + s_idx[w][s_ord[w][r]]] = -1.f;
        }
    } else {
        // correctness fallback (unreachable for this data): global-memory greedy
        float lastv = __int_as_float(0x7f800000);  // +inf
        int   lasti = -1;
        for (;;) {
            float bv = -1.f; int bix = -1;
            for (int i = lane; i < n; i += 32) {
                int idx = d_items[off + i];
                float s = g_score[b * NTOT + idx];
                if (s >= 0.f && (s < lastv || (s == lastv && idx > lasti))) {
                    if (s > bv || (s == bv && idx < bix)) { bv = s; bix = idx; }
                }
            }
            for (int o = 16; o; o >>= 1) {
                float ov = __shfl_down_sync(0xffffffffu, bv, o);
                int   oi = __shfl_down_sync(0xffffffffu, bix, o);
                if (oi >= 0 && (bix < 0 || ov > bv || (ov == bv && oi < bix))) {
                    bv = ov; bix = oi;
                }
            }
            bv  = __shfl_sync(0xffffffffu, bv, 0);
            bix = __shfl_sync(0xffffffffu, bix, 0);
            if (bix < 0) break;
            float4 pb = g_box[b * NTOT + bix];
            for (int i = lane; i < n; i += 32) {
                int idx = d_items[off + i];
                float s = g_score[b * NTOT + idx];
                if (idx != bix && s >= 0.f &&
                    (s < bv || (s == bv && idx > bix))) {
                    if (iou_(pb, g_box[b * NTOT + idx]) > 0.6f)
                        g_score[b * NTOT + idx] = -1.f;
                }
            }
            lastv = bv; lasti = bix;
            __syncwarp();
        }
    }
}

// ---------------------------------------------------------------------------
// Top-100 survivors per batch, descending. Histogram threshold + rank sort.
// ---------------------------------------------------------------------------
__global__ void __launch_bounds__(1024) topk_kernel(float* __restrict__ out) {
    __shared__ int   hist[1024];
    __shared__ float cs[CANDCAP];
    __shared__ int   cidx[CANDCAP];
    __shared__ int   s_cnt, s_t;

    int b = blockIdx.x, tid = threadIdx.x;
    hist[tid] = 0;
    if (tid == 0) { s_cnt = 0; s_t = 0; }
    __syncthreads();

    for (int a = tid; a < NTOT; a += 1024) {
        float s = g_score[b * NTOT + a];
        if (s >= 0.f) {
            int bin = min(1023, (int)(s * 1024.f));
            atomicAdd(&hist[bin], 1);
        }
    }
    __syncthreads();
    // suffix sum: hist[t] := count of scores in bins >= t
    for (int d = 1; d < 1024; d <<= 1) {
        int v = hist[tid] + (tid + d < 1024 ? hist[tid + d] : 0);
        __syncthreads();
        hist[tid] = v;
        __syncthreads();
    }
    // largest t with suffix >= POSTK (0 if fewer than POSTK survivors)
    if (hist[tid] >= POSTK && (tid == 1023 || hist[tid + 1] < POSTK)) s_t = tid;
    __syncthreads();
    int t = s_t;

    for (int a = tid; a < NTOT; a += 1024) {
        float s = g_score[b * NTOT + a];
        if (s >= 0.f) {
            int bin = min(1023, (int)(s * 1024.f));
            if (bin >= t) {
                int pos = atomicAdd(&s_cnt, 1);
                if (pos < CANDCAP) { cs[pos] = s; cidx[pos] = a; }
            }
        }
    }
    __syncthreads();
    int C = min(s_cnt, CANDCAP);

    for (int i = tid; i < C; i += 1024) {
        float si = cs[i];
        int   ai = cidx[i];
        int   r  = 0;
        for (int j = 0; j < C; j++) {
            float sj = cs[j];
            r += (sj > si) || (sj == si && cidx[j] < ai);
        }
        if (r < POSTK) {
            float4 bb  = g_box[b * NTOT + ai];
            float* det = out + ((size_t)b * POSTK + r) * 5;
            det[0] = bb.x; det[1] = bb.y; det[2] = bb.z; det[3] = bb.w;
            det[4] = si;
            out[(size_t)BATCH * POSTK * 5 + b * POSTK + r] =
                (float)(g_clspos[b * NTOT + ai] & 0xFF);
        }
    }
    // pad (only if fewer than 100 survivors — practically never)
    int valid = C < POSTK ? C : POSTK;
    for (int k = valid + tid; k < POSTK; k += 1024) {
        float* det = out + ((size_t)b * POSTK + k) * 5;
        det[0] = 0.f; det[1] = 0.f; det[2] = 0.f; det[3] = 0.f; det[4] = -1.f;
        out[(size_t)BATCH * POSTK * 5 + b * POSTK + k] = -1.f;
    }
}

// ---------------------------------------------------------------------------
extern "C" void kernel_launch(void* const* d_in, const int* in_sizes, int n_in,
                              void* d_out, int out_size) {
    (void)n_in; (void)out_size;

    LevelPtrs p;
    if (in_sizes[1] == 819200) {
        for (int i = 0; i < 5; i++) {          // interleaved (cls,box,ctr)/level
            p.cls[i] = (const float*)d_in[3 * i + 0];
            p.box[i] = (const float*)d_in[3 * i + 1];
            p.ctr[i] = (const float*)d_in[3 * i + 2];
        }
    } else {
        for (int i = 0; i < 5; i++) {          // planar cls x5, box x5, ctr x5
            p.cls[i] = (const float*)d_in[i];
            p.box[i] = (const float*)d_in[5 + i];
            p.ctr[i] = (const float*)d_in[10 + i];
        }
    }

    reset_kernel<<<(NBUCKET + 255) / 256, 256>>>();

    dim3 dgrid((NGROUP + 127) / 128, BATCH);
    decode_kernel<<<dgrid, 128>>>(p);

    scan_kernel<<<1, 1024>>>();

    scatter_kernel<<<(BATCH * NTOT + 255) / 256, 256>>>();

    nms_bucket_kernel<<<(NBUCKET + 1) / 2, 64>>>();

    topk_kernel<<<BATCH, 1024>>>((float*)d_out);
}

// round 4
// speedup vs baseline: 4.8018x; 4.3113x over previous
#include <cuda_runtime.h>
#include <math.h>

// ---------------------------------------------------------------------------
// FCOS post-processing, top-C candidate NMS.
//   Greedy suppression only flows from higher to lower scores, so the first
//   100 survivors are exactly determined by the top-C candidates provided
//   >=100 of them survive. C=512 first, widen to 2048 if needed.
// ---------------------------------------------------------------------------

#define BATCH   16
#define NCLS    80
#define NTOT    17064          // 12800 + 3200 + 800 + 208 + 56
#define NGROUP  (NTOT / 4)     // 4266
#define POSTK   100
#define CAP     4096           // candidate smem capacity
#define NT2     1024           // threads in select kernel

__device__ float         g_score[BATCH * NTOT];
__device__ unsigned char g_cls  [BATCH * NTOT];

struct LevelPtrs {
    const float* cls[5];
    const float* box[5];
    const float* ctr[5];
};

__constant__ int   c_off[6]    = {0, 12800, 16000, 16800, 17008, 17064};
__constant__ int   c_W[5]      = {128, 64, 32, 16, 8};
__constant__ float c_stride[5] = {8.f, 16.f, 32.f, 64.f, 128.f};

__device__ __forceinline__ float sigmoidf_(float x) {
    return 1.0f / (1.0f + expf(-x));
}

// ---------------------------------------------------------------------------
// Kernel 1: decode scores + classes. One thread per 4 consecutive anchors.
// ---------------------------------------------------------------------------
__global__ void decode_kernel(LevelPtrs p) {
    int g = blockIdx.x * blockDim.x + threadIdx.x;
    int b = blockIdx.y;
    if (g >= NGROUP) return;
    int a0 = g * 4;

    int lvl = (a0 >= 12800) + (a0 >= 16000) + (a0 >= 16800) + (a0 >= 17008);
    int hw0 = a0 - c_off[lvl];
    int HW  = c_off[lvl + 1] - c_off[lvl];
    int HW4 = HW >> 2;

    const float4* cp = reinterpret_cast<const float4*>(
        p.cls[lvl] + (size_t)b * NCLS * HW + hw0);
    float4 best = cp[0];
    int4   bi   = make_int4(0, 0, 0, 0);
#pragma unroll 4
    for (int c = 1; c < NCLS; c++) {
        float4 v = cp[(size_t)c * HW4];
        if (v.x > best.x) { best.x = v.x; bi.x = c; }
        if (v.y > best.y) { best.y = v.y; bi.y = c; }
        if (v.z > best.z) { best.z = v.z; bi.z = c; }
        if (v.w > best.w) { best.w = v.w; bi.w = c; }
    }

    float4 ct = *reinterpret_cast<const float4*>(p.ctr[lvl] + (size_t)b * HW + hw0);

    float4 s4;
    s4.x = sqrtf(sigmoidf_(best.x) * sigmoidf_(ct.x));
    s4.y = sqrtf(sigmoidf_(best.y) * sigmoidf_(ct.y));
    s4.z = sqrtf(sigmoidf_(best.z) * sigmoidf_(ct.z));
    s4.w = sqrtf(sigmoidf_(best.w) * sigmoidf_(ct.w));

    int gi = b * NTOT + a0;
    reinterpret_cast<float4*>(g_score)[gi >> 2] = s4;
    uchar4 c4 = make_uchar4((unsigned char)bi.x, (unsigned char)bi.y,
                            (unsigned char)bi.z, (unsigned char)bi.w);
    *reinterpret_cast<uchar4*>(&g_cls[gi]) = c4;
}

// ---------------------------------------------------------------------------
// Kernel 2: per-batch top-C select + greedy class-aware NMS + output.
// One block (1024 threads) per batch.
// ---------------------------------------------------------------------------
extern __shared__ char smem2[];

__global__ void __launch_bounds__(NT2, 1) select_nms_kernel(LevelPtrs p,
                                                            float* __restrict__ out) {
    // dynamic smem layout
    float4*        so_box = (float4*)smem2;                       // CAP * 16
    int*           hist   = (int*)(smem2 + CAP * 16);             // 1024 * 4
    float*         st_s   = (float*)((char*)hist + 4096);         // CAP * 4
    int*           st_i   = (int*)((char*)st_s + CAP * 4);        // CAP * 4
    float*         so_s   = (float*)((char*)st_i + CAP * 4);      // CAP * 4
    int*           so_i   = (int*)((char*)so_s + CAP * 4);        // CAP * 4
    unsigned char* so_c   = (unsigned char*)((char*)so_i + CAP * 4); // CAP
    unsigned char* keep   = so_c + CAP;                              // CAP

    __shared__ int s_t, s_C, s_kept;

    const int b   = blockIdx.x;
    const int tid = threadIdx.x;
    const float* gs = g_score + b * NTOT;

    // ---- histogram of all 17064 scores (all in [0,1)) --------------------
    hist[tid] = 0;
    __syncthreads();
    for (int a = tid; a < NTOT; a += NT2) {
        int bin = min(1023, max(0, (int)(gs[a] * 1024.f)));
        atomicAdd(&hist[bin], 1);
    }
    __syncthreads();
    // suffix sum: hist[t] = #scores in bins >= t
    for (int d = 1; d < 1024; d <<= 1) {
        int v = hist[tid] + (tid + d < 1024 ? hist[tid + d] : 0);
        __syncthreads();
        hist[tid] = v;
        __syncthreads();
    }

    int done_kept = 0;
    int done_stop = -1;

    for (int attempt = 0; attempt < 2; attempt++) {
        int target = attempt == 0 ? 512 : 2048;

        // ---- threshold bin: largest t with suffix >= target --------------
        if (tid == 0) s_t = 0;
        __syncthreads();
        if (hist[tid] >= target && (tid == 1023 || hist[tid + 1] < target))
            s_t = tid;
        __syncthreads();
        int t = s_t;
        if (t < 1023 && hist[t] > CAP) t = t + 1;  // cap guard (suffix(t+1) < target <= CAP)

        // ---- collect candidates ------------------------------------------
        if (tid == 0) s_C = 0;
        __syncthreads();
        for (int a = tid; a < NTOT; a += NT2) {
            float s = gs[a];
            int bin = min(1023, max(0, (int)(s * 1024.f)));
            if (bin >= t) {
                int pos = atomicAdd(&s_C, 1);
                if (pos < CAP) { st_s[pos] = s; st_i[pos] = a; }
            }
        }
        __syncthreads();
        int C = min(s_C, CAP);

        // ---- rank sort: score desc, anchor idx asc (== reference order) --
        for (int i = tid; i < C; i += NT2) {
            float si = st_s[i];
            int   ai = st_i[i];
            int   r  = 0;
            for (int j = 0; j < C; j++) {
                float sj = st_s[j];
                r += (sj > si) || (sj == si && st_i[j] < ai);
            }
            so_s[r] = si;
            so_i[r] = ai;
        }
        __syncthreads();

        // ---- recompute boxes + fetch class for sorted candidates ---------
        for (int i = tid; i < C; i += NT2) {
            int a = so_i[i];
            int lvl = (a >= 12800) + (a >= 16000) + (a >= 16800) + (a >= 17008);
            int   hw     = a - c_off[lvl];
            int   HW     = c_off[lvl + 1] - c_off[lvl];
            int   W      = c_W[lvl];
            float stride = c_stride[lvl];
            const float* bp = p.box[lvl] + (size_t)b * 4 * HW + hw;
            float l = bp[0]      * stride;
            float tt = bp[HW]    * stride;
            float r = bp[2 * HW] * stride;
            float d = bp[3 * HW] * stride;
            float px = (hw % W) * stride + 0.5f * stride;
            float py = (hw / W) * stride + 0.5f * stride;
            float x1 = fminf(fmaxf(px - l, 0.f), 1023.f);
            float y1 = fminf(fmaxf(py - tt, 0.f), 799.f);
            float x2 = fminf(fmaxf(px + r, 0.f), 1023.f);
            float y2 = fminf(fmaxf(py + d, 0.f), 799.f);
            so_box[i] = make_float4(x1, y1, x2, y2);
            so_c[i]   = g_cls[b * NTOT + a];
            keep[i]   = 1;
        }
        __syncthreads();

        // ---- greedy NMS in rank order, early exit at 100th survivor ------
        int kcount = 0;           // uniform across threads
        int stop   = C - 1;
        for (int r = 0; r < C; r++) {
            int kr = keep[r];     // uniform (same smem address for all)
            if (kr) {
                float4 pb = so_box[r];
                unsigned char pc = so_c[r];
                float pa = (pb.z - pb.x) * (pb.w - pb.y);
                for (int i = r + 1 + tid; i < C; i += NT2) {
                    if (keep[i] && so_c[i] == pc) {
                        float4 qb = so_box[i];
                        float ix1 = fmaxf(pb.x, qb.x), iy1 = fmaxf(pb.y, qb.y);
                        float ix2 = fminf(pb.z, qb.z), iy2 = fminf(pb.w, qb.w);
                        float inter = fmaxf(ix2 - ix1, 0.f) * fmaxf(iy2 - iy1, 0.f);
                        float qa = (qb.z - qb.x) * (qb.w - qb.y);
                        if (inter / (pa + qa - inter + 1e-9f) > 0.6f) keep[i] = 0;
                    }
                }
            }
            __syncthreads();
            if (kr && ++kcount >= POSTK) { stop = r; break; }
        }

        // ---- survivor count over [0, stop] -------------------------------
        if (tid == 0) s_kept = 0;
        __syncthreads();
        {
            int loc = 0;
            for (int i = tid; i <= stop; i += NT2) loc += keep[i];
            if (loc) atomicAdd(&s_kept, loc);
        }
        __syncthreads();
        int kept = s_kept;

        bool enough    = kept >= POSTK;
        bool exhausted = (C >= NTOT) || (s_C <= C && t == 0);
        if (enough || exhausted || attempt == 1) {
            // ---- output: rank survivors, write top-100 -------------------
            for (int i = tid; i <= stop; i += NT2) {
                if (keep[i]) {
                    int rk = 0;
                    for (int j = 0; j < i; j++) rk += keep[j];
                    if (rk < POSTK) {
                        float4 bb  = so_box[i];
                        float* det = out + ((size_t)b * POSTK + rk) * 5;
                        det[0] = bb.x; det[1] = bb.y;
                        det[2] = bb.z; det[3] = bb.w;
                        det[4] = so_s[i];
                        out[(size_t)BATCH * POSTK * 5 + b * POSTK + rk] =
                            (float)so_c[i];
                    }
                }
            }
            done_kept = kept < POSTK ? kept : POSTK;
            done_stop = stop;
            break;
        }
        __syncthreads();  // before hist/t reuse in next attempt
    }

    // ---- pad (only if fewer than 100 survivors — practically never) ------
    for (int k = done_kept + tid; k < POSTK; k += NT2) {
        float* det = out + ((size_t)b * POSTK + k) * 5;
        det[0] = 0.f; det[1] = 0.f; det[2] = 0.f; det[3] = 0.f; det[4] = -1.f;
        out[(size_t)BATCH * POSTK * 5 + b * POSTK + k] = -1.f;
    }
    (void)done_stop;
}

// ---------------------------------------------------------------------------
extern "C" void kernel_launch(void* const* d_in, const int* in_sizes, int n_in,
                              void* d_out, int out_size) {
    (void)n_in; (void)out_size;

    LevelPtrs p;
    if (in_sizes[1] == 819200) {
        for (int i = 0; i < 5; i++) {          // interleaved (cls,box,ctr)/level
            p.cls[i] = (const float*)d_in[3 * i + 0];
            p.box[i] = (const float*)d_in[3 * i + 1];
            p.ctr[i] = (const float*)d_in[3 * i + 2];
        }
    } else {
        for (int i = 0; i < 5; i++) {          // planar cls x5, box x5, ctr x5
            p.cls[i] = (const float*)d_in[i];
            p.box[i] = (const float*)d_in[5 + i];
            p.ctr[i] = (const float*)d_in[10 + i];
        }
    }

    // smem for select kernel: box(64K) + hist(4K) + 4*CAP*4 (64K) + 2*CAP (8K)
    const int smem_bytes = CAP * 16 + 4096 + 4 * CAP * 4 + 2 * CAP;
    cudaFuncSetAttribute(select_nms_kernel,
                         cudaFuncAttributeMaxDynamicSharedMemorySize, smem_bytes);

    dim3 dgrid((NGROUP + 255) / 256, BATCH);
    decode_kernel<<<dgrid, 256>>>(p);

    select_nms_kernel<<<BATCH, NT2, smem_bytes>>>(p, (float*)d_out);
}

// round 6
// speedup vs baseline: 6.3079x; 1.3137x over previous
#include <cuda_runtime.h>
#include <math.h>

// ---------------------------------------------------------------------------
// FCOS post-processing, top-C candidate NMS with per-class parallel greedy.
//   Greedy suppression is intra-class and flows strictly down the global
//   score ranking, so: (1) the first 100 survivors are determined by the
//   top-C candidates provided >=100 of them survive (C=512, widen 2048);
//   (2) per-class NMS of the rank-sorted candidates == global greedy NMS.
// ---------------------------------------------------------------------------

#define BATCH   16
#define NCLS    80
#define NTOT    17064          // 12800 + 3200 + 800 + 208 + 56
#define NGROUP  (NTOT / 4)     // 4266
#define POSTK   100
#define CAP     4096           // candidate smem capacity
#define CLSCAP  256            // per-class list capacity
#define NT2     1024

__device__ float         g_score[BATCH * NTOT];
__device__ unsigned char g_cls  [BATCH * NTOT];

struct LevelPtrs {
    const float* cls[5];
    const float* box[5];
    const float* ctr[5];
};

__constant__ int   c_off[6]    = {0, 12800, 16000, 16800, 17008, 17064};
__constant__ int   c_W[5]      = {128, 64, 32, 16, 8};
__constant__ float c_stride[5] = {8.f, 16.f, 32.f, 64.f, 128.f};

__device__ __forceinline__ float sigmoidf_(float x) {
    return 1.0f / (1.0f + expf(-x));
}

// ---------------------------------------------------------------------------
// Kernel 1: decode scores + classes. One thread per 4 consecutive anchors.
// ---------------------------------------------------------------------------
__global__ void decode_kernel(LevelPtrs p) {
    int g = blockIdx.x * blockDim.x + threadIdx.x;
    int b = blockIdx.y;
    if (g >= NGROUP) return;
    int a0 = g * 4;

    int lvl = (a0 >= 12800) + (a0 >= 16000) + (a0 >= 16800) + (a0 >= 17008);
    int hw0 = a0 - c_off[lvl];
    int HW  = c_off[lvl + 1] - c_off[lvl];
    int HW4 = HW >> 2;

    const float4* __restrict__ cp = reinterpret_cast<const float4*>(
        p.cls[lvl] + (size_t)b * NCLS * HW + hw0);
    float4 best = cp[0];
    int4   bi   = make_int4(0, 0, 0, 0);
#pragma unroll 8
    for (int c = 1; c < NCLS; c++) {
        float4 v = cp[(size_t)c * HW4];
        if (v.x > best.x) { best.x = v.x; bi.x = c; }
        if (v.y > best.y) { best.y = v.y; bi.y = c; }
        if (v.z > best.z) { best.z = v.z; bi.z = c; }
        if (v.w > best.w) { best.w = v.w; bi.w = c; }
    }

    float4 ct = *reinterpret_cast<const float4*>(p.ctr[lvl] + (size_t)b * HW + hw0);

    float4 s4;
    s4.x = sqrtf(sigmoidf_(best.x) * sigmoidf_(ct.x));
    s4.y = sqrtf(sigmoidf_(best.y) * sigmoidf_(ct.y));
    s4.z = sqrtf(sigmoidf_(best.z) * sigmoidf_(ct.z));
    s4.w = sqrtf(sigmoidf_(best.w) * sigmoidf_(ct.w));

    int gi = b * NTOT + a0;
    reinterpret_cast<float4*>(g_score)[gi >> 2] = s4;
    *reinterpret_cast<uchar4*>(&g_cls[gi]) =
        make_uchar4((unsigned char)bi.x, (unsigned char)bi.y,
                    (unsigned char)bi.z, (unsigned char)bi.w);
}

// ---------------------------------------------------------------------------
// Kernel 2: per-batch select + per-class parallel NMS + output.
// One block (1024 threads) per batch.
// ---------------------------------------------------------------------------
extern __shared__ char smem2[];

__global__ void __launch_bounds__(NT2, 1) select_nms_kernel(LevelPtrs p,
                                                            float* __restrict__ out) {
    float4*         so_box   = (float4*)smem2;                         // 64K
    int*            hist     = (int*)(smem2 + CAP * 16);               // 4K
    float*          st_s     = (float*)((char*)hist + 4096);           // 16K
    int*            st_i     = (int*)((char*)st_s + CAP * 4);          // 16K
    float*          so_s     = (float*)((char*)st_i + CAP * 4);        // 16K
    int*            so_i     = (int*)((char*)so_s + CAP * 4);          // 16K
    unsigned char*  so_c     = (unsigned char*)((char*)so_i + CAP * 4);// 4K
    unsigned char*  keep     = so_c + CAP;                             // 4K
    unsigned short* cls_list = (unsigned short*)(keep + CAP);          // 40K

    __shared__ int s_part[32];
    __shared__ int s_ccnt[NCLS];
    __shared__ int s_t, s_C, s_kept, s_ovf;

    const int b    = blockIdx.x;
    const int tid  = threadIdx.x;
    const int warp = tid >> 5;
    const int lane = tid & 31;
    const float* __restrict__ gs = g_score + b * NTOT;

    // ---- histogram of all 17064 scores (scores in [0,1)) -----------------
    hist[tid] = 0;
    __syncthreads();
    for (int a = tid; a < NTOT; a += NT2) {
        int bin = min(1023, max(0, (int)(gs[a] * 1024.f)));
        atomicAdd(&hist[bin], 1);
    }
    __syncthreads();

    // ---- suffix sum via warp shuffles (3 barriers) -----------------------
    {
        int val = hist[tid];
#pragma unroll
        for (int off = 1; off < 32; off <<= 1) {
            int v = __shfl_down_sync(0xffffffffu, val, off);
            if (lane + off < 32) val += v;
        }
        if (lane == 0) s_part[warp] = val;   // chunk totals
        __syncthreads();
        if (warp == 0) {
            int pv = s_part[lane];
#pragma unroll
            for (int off = 1; off < 32; off <<= 1) {
                int v = __shfl_down_sync(0xffffffffu, pv, off);
                if (lane + off < 32) pv += v;
            }
            int excl = __shfl_down_sync(0xffffffffu, pv, 1);  // chunks after w
            if (lane == 31) excl = 0;
            s_part[lane] = excl;
        }
        __syncthreads();
        hist[tid] = val + s_part[warp];      // suffix count of bins >= tid
        __syncthreads();
    }

    int done_kept = 0;

    for (int attempt = 0; attempt < 2; attempt++) {
        int target = attempt == 0 ? 512 : 2048;

        // ---- threshold bin: largest t with suffix >= target --------------
        if (tid == 0) { s_t = 0; s_C = 0; s_ovf = 0; }
        __syncthreads();
        if (hist[tid] >= target && (tid == 1023 || hist[tid + 1] < target))
            s_t = tid;
        __syncthreads();
        int t = s_t;
        if (t < 1023 && hist[t] > CAP) t = t + 1;  // suffix(t+1) < target <= CAP

        // ---- collect candidates ------------------------------------------
        for (int a = tid; a < NTOT; a += NT2) {
            float s = gs[a];
            int bin = min(1023, max(0, (int)(s * 1024.f)));
            if (bin >= t) {
                int pos = atomicAdd(&s_C, 1);
                if (pos < CAP) { st_s[pos] = s; st_i[pos] = a; }
            }
        }
        __syncthreads();
        int C = min(s_C, CAP);

        // ---- rank sort: score desc, anchor idx asc (== reference order) --
        for (int i = tid; i < C; i += NT2) {
            float si = st_s[i];
            int   ai = st_i[i];
            int   r  = 0;
            for (int j = 0; j < C; j++) {
                float sj = st_s[j];
                r += (sj > si) || (sj == si && st_i[j] < ai);
            }
            so_s[r] = si;
            so_i[r] = ai;
        }
        __syncthreads();

        // ---- recompute boxes + class for sorted candidates ---------------
        for (int i = tid; i < C; i += NT2) {
            int a = so_i[i];
            int lvl = (a >= 12800) + (a >= 16000) + (a >= 16800) + (a >= 17008);
            int   hw     = a - c_off[lvl];
            int   HW     = c_off[lvl + 1] - c_off[lvl];
            int   W      = c_W[lvl];
            float stride = c_stride[lvl];
            const float* bp = p.box[lvl] + (size_t)b * 4 * HW + hw;
            float l  = bp[0]      * stride;
            float tt = bp[HW]     * stride;
            float r  = bp[2 * HW] * stride;
            float d  = bp[3 * HW] * stride;
            float px = (hw % W) * stride + 0.5f * stride;
            float py = (hw / W) * stride + 0.5f * stride;
            so_box[i] = make_float4(fminf(fmaxf(px - l, 0.f), 1023.f),
                                    fminf(fmaxf(py - tt, 0.f), 799.f),
                                    fminf(fmaxf(px + r, 0.f), 1023.f),
                                    fminf(fmaxf(py + d, 0.f), 799.f));
            so_c[i] = g_cls[b * NTOT + a];
            keep[i] = 1;
        }
        __syncthreads();

        // ---- per-class compaction (warp ballot, rank order preserved) ----
        for (int c = warp; c < NCLS; c += 32) {
            int m = 0;
            for (int base = 0; base < C; base += 32) {
                int i = base + lane;
                bool pr = (i < C) && (so_c[i] == (unsigned char)c);
                unsigned mask = __ballot_sync(0xffffffffu, pr);
                if (pr) {
                    int pos = m + __popc(mask & ((1u << lane) - 1));
                    if (pos < CLSCAP)
                        cls_list[c * CLSCAP + pos] = (unsigned short)i;
                }
                m += __popc(mask);
            }
            if (lane == 0) {
                s_ccnt[c] = m;
                if (m > CLSCAP) atomicExch(&s_ovf, 1);
            }
        }
        __syncthreads();

        int stop = C - 1;
        if (!s_ovf) {
            // ---- per-class greedy NMS, warp-local (no block barriers) ----
            for (int c = warp; c < NCLS; c += 32) {
                int m = s_ccnt[c];
                const unsigned short* L = cls_list + c * CLSCAP;
                for (int r = 0; r < m; r++) {
                    int ir = L[r];
                    if (keep[ir]) {
                        float4 pb = so_box[ir];
                        float  pa = (pb.z - pb.x) * (pb.w - pb.y);
                        for (int j = r + 1 + lane; j < m; j += 32) {
                            int ij = L[j];
                            if (keep[ij]) {
                                float4 qb = so_box[ij];
                                float ix1 = fmaxf(pb.x, qb.x), iy1 = fmaxf(pb.y, qb.y);
                                float ix2 = fminf(pb.z, qb.z), iy2 = fminf(pb.w, qb.w);
                                float inter = fmaxf(ix2 - ix1, 0.f) * fmaxf(iy2 - iy1, 0.f);
                                float qa = (qb.z - qb.x) * (qb.w - qb.y);
                                if (inter / (pa + qa - inter + 1e-9f) > 0.6f)
                                    keep[ij] = 0;
                            }
                        }
                    }
                    __syncwarp();
                }
            }
            __syncthreads();
        } else {
            // ---- fallback: serial block-wide greedy (always correct) -----
            int kcount = 0;
            for (int r = 0; r < C; r++) {
                int kr = keep[r];
                if (kr) {
                    float4 pb = so_box[r];
                    unsigned char pc = so_c[r];
                    float pa = (pb.z - pb.x) * (pb.w - pb.y);
                    for (int i = r + 1 + tid; i < C; i += NT2) {
                        if (keep[i] && so_c[i] == pc) {
                            float4 qb = so_box[i];
                            float ix1 = fmaxf(pb.x, qb.x), iy1 = fmaxf(pb.y, qb.y);
                            float ix2 = fminf(pb.z, qb.z), iy2 = fminf(pb.w, qb.w);
                            float inter = fmaxf(ix2 - ix1, 0.f) * fmaxf(iy2 - iy1, 0.f);
                            float qa = (qb.z - qb.x) * (qb.w - qb.y);
                            if (inter / (pa + qa - inter + 1e-9f) > 0.6f) keep[i] = 0;
                        }
                    }
                }
                __syncthreads();
                if (kr && ++kcount >= POSTK) { stop = r; break; }
            }
        }

        // ---- survivor count over [0, stop] -------------------------------
        if (tid == 0) s_kept = 0;
        __syncthreads();
        {
            int loc = 0;
            for (int i = tid; i <= stop; i += NT2) loc += keep[i];
#pragma unroll
            for (int off = 16; off; off >>= 1)
                loc += __shfl_down_sync(0xffffffffu, loc, off);
            if (lane == 0 && loc) atomicAdd(&s_kept, loc);
        }
        __syncthreads();
        int kept = s_kept;

        bool enough    = kept >= POSTK;
        bool exhausted = (C >= NTOT) || (s_C <= C && t == 0);
        if (enough || exhausted || attempt == 1) {
            for (int i = tid; i <= stop; i += NT2) {
                if (keep[i]) {
                    int rk = 0;
                    for (int j = 0; j < i; j++) rk += keep[j];
                    if (rk < POSTK) {
                        float4 bb  = so_box[i];
                        float* det = out + ((size_t)b * POSTK + rk) * 5;
                        det[0] = bb.x; det[1] = bb.y;
                        det[2] = bb.z; det[3] = bb.w;
                        det[4] = so_s[i];
                        out[(size_t)BATCH * POSTK * 5 + b * POSTK + rk] =
                            (float)so_c[i];
                    }
                }
            }
            done_kept = kept < POSTK ? kept : POSTK;
            break;
        }
        __syncthreads();
    }

    // ---- pad (only if fewer than 100 survivors — practically never) ------
    for (int k = done_kept + tid; k < POSTK; k += NT2) {
        float* det = out + ((size_t)b * POSTK + k) * 5;
        det[0] = 0.f; det[1] = 0.f; det[2] = 0.f; det[3] = 0.f; det[4] = -1.f;
        out[(size_t)BATCH * POSTK * 5 + b * POSTK + k] = -1.f;
    }
}

// ---------------------------------------------------------------------------
extern "C" void kernel_launch(void* const* d_in, const int* in_sizes, int n_in,
                              void* d_out, int out_size) {
    (void)n_in; (void)out_size;

    LevelPtrs p;
    if (in_sizes[1] == 819200) {
        for (int i = 0; i < 5; i++) {          // interleaved (cls,box,ctr)/level
            p.cls[i] = (const float*)d_in[3 * i + 0];
            p.box[i] = (const float*)d_in[3 * i + 1];
            p.ctr[i] = (const float*)d_in[3 * i + 2];
        }
    } else {
        for (int i = 0; i < 5; i++) {          // planar cls x5, box x5, ctr x5
            p.cls[i] = (const float*)d_in[i];
            p.box[i] = (const float*)d_in[5 + i];
            p.ctr[i] = (const float*)d_in[10 + i];
        }
    }

    const int smem_bytes = CAP * 16 + 4096 + 4 * CAP * 4 + 2 * CAP
                         + NCLS * CLSCAP * 2;   // = 184320
    cudaFuncSetAttribute(select_nms_kernel,
                         cudaFuncAttributeMaxDynamicSharedMemorySize, smem_bytes);

    dim3 dgrid((NGROUP + 255) / 256, BATCH);
    decode_kernel<<<dgrid, 256>>>(p);

    select_nms_kernel<<<BATCH, NT2, smem_bytes>>>(p, (float*)d_out);
}

// round 8
// speedup vs baseline: 6.3536x; 1.0072x over previous
#include <cuda_runtime.h>
#include <math.h>

// ---------------------------------------------------------------------------
// FCOS post-processing, top-C candidate NMS, sort-free main path.
//   (1) Greedy suppression flows strictly down the global score ranking and is
//       intra-class, so the first 100 survivors are determined by the top-C
//       candidates provided >=100 of them survive (C=512, widen to 2048).
//   (2) Per-class NMS of per-class-sorted candidates == global greedy NMS.
//   (3) Output order == survivors ranked by (score desc, anchor idx asc).
// ---------------------------------------------------------------------------

#define BATCH   16
#define NCLS    80
#define NTOT    17064          // 12800 + 3200 + 800 + 208 + 56
#define NGROUP  (NTOT / 4)     // 4266
#define POSTK   100
#define CAP     4096           // candidate slot capacity
#define CLSCAP  64             // per-class list capacity
#define SVCAP   4096           // survivor list capacity
#define NT2     1024

__device__ float         g_score[BATCH * NTOT];
__device__ unsigned char g_cls  [BATCH * NTOT];

struct LevelPtrs {
    const float* cls[5];
    const float* box[5];
    const float* ctr[5];
};

__constant__ int   c_off[6]    = {0, 12800, 16000, 16800, 17008, 17064};
__constant__ int   c_W[5]      = {128, 64, 32, 16, 8};
__constant__ float c_stride[5] = {8.f, 16.f, 32.f, 64.f, 128.f};

__device__ __forceinline__ float sigmoidf_(float x) {
    return 1.0f / (1.0f + expf(-x));
}
__device__ __forceinline__ float iou_(const float4 a, const float4 b) {
    float ix1 = fmaxf(a.x, b.x), iy1 = fmaxf(a.y, b.y);
    float ix2 = fminf(a.z, b.z), iy2 = fminf(a.w, b.w);
    float inter = fmaxf(ix2 - ix1, 0.f) * fmaxf(iy2 - iy1, 0.f);
    float aa = (a.z - a.x) * (a.w - a.y);
    float ab = (b.z - b.x) * (b.w - b.y);
    return inter / (aa + ab - inter + 1e-9f);
}

// ---------------------------------------------------------------------------
// Kernel 1: decode scores + classes. One thread per 4 consecutive anchors.
// ---------------------------------------------------------------------------
__global__ void decode_kernel(LevelPtrs p) {
    int g = blockIdx.x * blockDim.x + threadIdx.x;
    int b = blockIdx.y;
    if (g >= NGROUP) return;
    int a0 = g * 4;

    int lvl = (a0 >= 12800) + (a0 >= 16000) + (a0 >= 16800) + (a0 >= 17008);
    int hw0 = a0 - c_off[lvl];
    int HW  = c_off[lvl + 1] - c_off[lvl];
    int HW4 = HW >> 2;

    const float4* __restrict__ cp = reinterpret_cast<const float4*>(
        p.cls[lvl] + (size_t)b * NCLS * HW + hw0);
    float4 best = cp[0];
    int4   bi   = make_int4(0, 0, 0, 0);
#pragma unroll 8
    for (int c = 1; c < NCLS; c++) {
        float4 v = cp[(size_t)c * HW4];
        if (v.x > best.x) { best.x = v.x; bi.x = c; }
        if (v.y > best.y) { best.y = v.y; bi.y = c; }
        if (v.z > best.z) { best.z = v.z; bi.z = c; }
        if (v.w > best.w) { best.w = v.w; bi.w = c; }
    }

    float4 ct = *reinterpret_cast<const float4*>(p.ctr[lvl] + (size_t)b * HW + hw0);

    float4 s4;
    s4.x = sqrtf(sigmoidf_(best.x) * sigmoidf_(ct.x));
    s4.y = sqrtf(sigmoidf_(best.y) * sigmoidf_(ct.y));
    s4.z = sqrtf(sigmoidf_(best.z) * sigmoidf_(ct.z));
    s4.w = sqrtf(sigmoidf_(best.w) * sigmoidf_(ct.w));

    int gi = b * NTOT + a0;
    reinterpret_cast<float4*>(g_score)[gi >> 2] = s4;
    *reinterpret_cast<uchar4*>(&g_cls[gi]) =
        make_uchar4((unsigned char)bi.x, (unsigned char)bi.y,
                    (unsigned char)bi.z, (unsigned char)bi.w);
}

// ---------------------------------------------------------------------------
// Kernel 2: per-batch select + per-class NMS + survivor top-100 output.
// One block (1024 threads) per batch.
// ---------------------------------------------------------------------------
extern __shared__ char smem2[];

__global__ void __launch_bounds__(NT2, 1) select_nms_kernel(LevelPtrs p,
                                                            float* __restrict__ out) {
    float4*         so_box   = (float4*)smem2;                          // 64K
    int*            hist     = (int*)(smem2 + CAP * 16);                // 4K
    float*          st_s     = (float*)((char*)hist + 4096);            // 16K
    int*            st_i     = (int*)((char*)st_s + CAP * 4);           // 16K
    unsigned char*  st_c     = (unsigned char*)((char*)st_i + CAP * 4); // 4K
    unsigned char*  keep     = st_c + CAP;                              // 4K
    unsigned short* cls_list = (unsigned short*)(keep + CAP);           // 10K
    unsigned short* sv       = cls_list + NCLS * CLSCAP;                // 8K

    __shared__ int s_part[32];
    __shared__ int s_ccnt[NCLS];
    __shared__ int s_t, s_C, s_ovf, s_nsurv;
    __shared__ float  s_pv;
    __shared__ int    s_ps;
    __shared__ float4 s_pb;

    const int b    = blockIdx.x;
    const int tid  = threadIdx.x;
    const int warp = tid >> 5;
    const int lane = tid & 31;
    const float4* __restrict__ gs4 =
        reinterpret_cast<const float4*>(g_score + b * NTOT);

    // ---- histogram of all scores (scores in [0,1)), float4 sweep ----------
    hist[tid] = 0;
    __syncthreads();
    for (int g = tid; g < NGROUP; g += NT2) {
        float4 v = gs4[g];
        atomicAdd(&hist[min(1023, max(0, (int)(v.x * 1024.f)))], 1);
        atomicAdd(&hist[min(1023, max(0, (int)(v.y * 1024.f)))], 1);
        atomicAdd(&hist[min(1023, max(0, (int)(v.z * 1024.f)))], 1);
        atomicAdd(&hist[min(1023, max(0, (int)(v.w * 1024.f)))], 1);
    }
    __syncthreads();

    // ---- suffix sum via warp shuffles (3 barriers) ------------------------
    {
        int val = hist[tid];
#pragma unroll
        for (int off = 1; off < 32; off <<= 1) {
            int v = __shfl_down_sync(0xffffffffu, val, off);
            if (lane + off < 32) val += v;
        }
        if (lane == 0) s_part[warp] = val;
        __syncthreads();
        if (warp == 0) {
            int pv = s_part[lane];
#pragma unroll
            for (int off = 1; off < 32; off <<= 1) {
                int v = __shfl_down_sync(0xffffffffu, pv, off);
                if (lane + off < 32) pv += v;
            }
            int excl = __shfl_down_sync(0xffffffffu, pv, 1);
            if (lane == 31) excl = 0;
            s_part[lane] = excl;
        }
        __syncthreads();
        hist[tid] = val + s_part[warp];  // suffix count of bins >= tid
        __syncthreads();
    }

    int done_kept = 0;

    for (int attempt = 0; attempt < 2; attempt++) {
        int target = attempt == 0 ? 512 : 2048;

        // ---- threshold bin: largest t with suffix >= target ---------------
        if (tid == 0) { s_t = 0; s_C = 0; s_ovf = 0; s_nsurv = 0; }
        __syncthreads();
        if (hist[tid] >= target && (tid == 1023 || hist[tid + 1] < target))
            s_t = tid;
        __syncthreads();
        int t = s_t;
        if (t < 1023 && hist[t] > CAP) t = t + 1;  // suffix(t+1) < target <= CAP

        // ---- collect candidates (unsorted slots), float4 sweep ------------
        for (int g = tid; g < NGROUP; g += NT2) {
            float4 v = gs4[g];
            float sv4[4] = {v.x, v.y, v.z, v.w};
#pragma unroll
            for (int j = 0; j < 4; j++) {
                float s = sv4[j];
                if (min(1023, max(0, (int)(s * 1024.f))) >= t) {
                    int pos = atomicAdd(&s_C, 1);
                    if (pos < CAP) {
                        int a = g * 4 + j;
                        st_s[pos] = s;
                        st_i[pos] = a;
                        st_c[pos] = g_cls[b * NTOT + a];
                    }
                }
            }
        }
        __syncthreads();
        int C = min(s_C, CAP);

        // ---- boxes per slot, keep=1 ---------------------------------------
        for (int i = tid; i < C; i += NT2) {
            int a = st_i[i];
            int lvl = (a >= 12800) + (a >= 16000) + (a >= 16800) + (a >= 17008);
            int   hw     = a - c_off[lvl];
            int   HW     = c_off[lvl + 1] - c_off[lvl];
            int   W      = c_W[lvl];
            float stride = c_stride[lvl];
            const float* bp = p.box[lvl] + (size_t)b * 4 * HW + hw;
            float l  = bp[0]      * stride;
            float tt = bp[HW]     * stride;
            float r  = bp[2 * HW] * stride;
            float d  = bp[3 * HW] * stride;
            float px = (hw % W) * stride + 0.5f * stride;
            float py = (hw / W) * stride + 0.5f * stride;
            so_box[i] = make_float4(fminf(fmaxf(px - l, 0.f), 1023.f),
                                    fminf(fmaxf(py - tt, 0.f), 799.f),
                                    fminf(fmaxf(px + r, 0.f), 1023.f),
                                    fminf(fmaxf(py + d, 0.f), 799.f));
            keep[i] = 1;
        }
        __syncthreads();

        // ---- per-class compaction (warp ballot over slot order) -----------
        for (int c = warp; c < NCLS; c += 32) {
            int m = 0;
            for (int base = 0; base < C; base += 32) {
                int i = base + lane;
                bool pr = (i < C) && (st_c[i] == (unsigned char)c);
                unsigned mask = __ballot_sync(0xffffffffu, pr);
                if (pr) {
                    int pos = m + __popc(mask & ((1u << lane) - 1));
                    if (pos < CLSCAP)
                        cls_list[c * CLSCAP + pos] = (unsigned short)i;
                }
                m += __popc(mask);
            }
            if (lane == 0) {
                s_ccnt[c] = m;
                if (m > CLSCAP) atomicExch(&s_ovf, 1);
            }
        }
        __syncthreads();

        if (!s_ovf) {
            // ---- per-class: sort by (score desc, idx asc) then greedy NMS -
            for (int c = warp; c < NCLS; c += 32) {
                int m = s_ccnt[c];
                unsigned short* L = cls_list + c * CLSCAP;
                // rank sort (m <= 64 -> at most 2 items per lane)
                int slotA[2], rA[2], cnt = 0;
                for (int i = lane; i < m; i += 32) {
                    int   sl = L[i];
                    float si = st_s[sl];
                    int   ai = st_i[sl];
                    int   r  = 0;
                    for (int j = 0; j < m; j++) {
                        int   s2 = L[j];
                        float sj = st_s[s2];
                        r += (sj > si) || (sj == si && st_i[s2] < ai);
                    }
                    slotA[cnt] = sl; rA[cnt] = r; cnt++;
                }
                __syncwarp();
                for (int q = 0; q < cnt; q++) L[rA[q]] = (unsigned short)slotA[q];
                __syncwarp();
                // greedy
                for (int r = 0; r < m; r++) {
                    int ir = L[r];
                    if (keep[ir]) {
                        float4 pb = so_box[ir];
                        for (int j = r + 1 + lane; j < m; j += 32) {
                            int ij = L[j];
                            if (keep[ij] && iou_(pb, so_box[ij]) > 0.6f)
                                keep[ij] = 0;
                        }
                    }
                    __syncwarp();
                }
            }
            __syncthreads();
        } else {
            // ---- fallback: block-serial class-aware greedy (unreachable) --
            for (int i = tid; i < C; i += NT2) keep[i] = 0;
            __syncthreads();
            for (int k = 0; k < POSTK; k++) {
                // argmax over st_s with idx tie-break
                float bv = -INFINITY; int bs = -1, ba = 0x7fffffff;
                for (int i = tid; i < C; i += NT2) {
                    float s = st_s[i];
                    int   a = st_i[i];
                    if (s > bv || (s == bv && a < ba)) { bv = s; bs = i; ba = a; }
                }
#pragma unroll
                for (int off = 16; off; off >>= 1) {
                    float ov = __shfl_down_sync(0xffffffffu, bv, off);
                    int   os = __shfl_down_sync(0xffffffffu, bs, off);
                    int   oa = __shfl_down_sync(0xffffffffu, ba, off);
                    if (os >= 0 && (ov > bv || (ov == bv && oa < ba))) {
                        bv = ov; bs = os; ba = oa;
                    }
                }
                if (lane == 0) { s_part[warp] = bs; ((float*)hist)[warp] = bv; }
                __syncthreads();
                if (tid == 0) {
                    float fv = -INFINITY; int fs = -1, fa = 0x7fffffff;
                    for (int w2 = 0; w2 < 32; w2++) {
                        int cs = s_part[w2];
                        if (cs >= 0) {
                            float cv = ((float*)hist)[w2];
                            int   ca = st_i[cs];
                            if (cv > fv || (cv == fv && ca < fa)) {
                                fv = cv; fs = cs; fa = ca;
                            }
                        }
                    }
                    s_pv = fv; s_ps = fs;
                    if (fs >= 0) { s_pb = so_box[fs]; keep[fs] = 1; st_s[fs] = -INFINITY; }
                }
                __syncthreads();
                if (s_ps < 0 || s_pv == -INFINITY) break;
                float4 pb = s_pb;
                unsigned char pc = st_c[s_ps];
                for (int i = tid; i < C; i += NT2) {
                    if (st_s[i] != -INFINITY && st_c[i] == pc &&
                        iou_(pb, so_box[i]) > 0.6f)
                        st_s[i] = -INFINITY;
                }
                __syncthreads();
            }
            // restore scores for survivors from g_score for ranking
            for (int i = tid; i < C; i += NT2)
                if (keep[i]) st_s[i] = g_score[b * NTOT + st_i[i]];
            __syncthreads();
        }

        // ---- survivor collection ------------------------------------------
        for (int i = tid; i < C; i += NT2) {
            if (keep[i]) {
                int pos = atomicAdd(&s_nsurv, 1);
                if (pos < SVCAP) sv[pos] = (unsigned short)i;
            }
        }
        __syncthreads();
        int S = min(s_nsurv, SVCAP);

        bool enough    = S >= POSTK;
        bool exhausted = (C >= NTOT) || (s_C <= C && t == 0);
        if (enough || exhausted || attempt == 1) {
            // ---- rank survivors by (score desc, idx asc), write top-100 ---
            for (int i = tid; i < S; i += NT2) {
                int   sl = sv[i];
                float si = st_s[sl];
                int   ai = st_i[sl];
                int   r  = 0;
                for (int j = 0; j < S; j++) {
                    int   s2 = sv[j];
                    float sj = st_s[s2];
                    r += (sj > si) || (sj == si && st_i[s2] < ai);
                }
                if (r < POSTK) {
                    float4 bb  = so_box[sl];
                    float* det = out + ((size_t)b * POSTK + r) * 5;
                    det[0] = bb.x; det[1] = bb.y;
                    det[2] = bb.z; det[3] = bb.w;
                    det[4] = si;
                    out[(size_t)BATCH * POSTK * 5 + b * POSTK + r] =
                        (float)st_c[sl];
                }
            }
            done_kept = S < POSTK ? S : POSTK;
            break;
        }
        __syncthreads();
    }

    // ---- pad (only if fewer than 100 survivors — practically never) -------
    for (int k = done_kept + tid; k < POSTK; k += NT2) {
        float* det = out + ((size_t)b * POSTK + k) * 5;
        det[0] = 0.f; det[1] = 0.f; det[2] = 0.f; det[3] = 0.f; det[4] = -1.f;
        out[(size_t)BATCH * POSTK * 5 + b * POSTK + k] = -1.f;
    }
}

// ---------------------------------------------------------------------------
extern "C" void kernel_launch(void* const* d_in, const int* in_sizes, int n_in,
                              void* d_out, int out_size) {
    (void)n_in; (void)out_size;

    LevelPtrs p;
    if (in_sizes[1] == 819200) {
        for (int i = 0; i < 5; i++) {          // interleaved (cls,box,ctr)/level
            p.cls[i] = (const float*)d_in[3 * i + 0];
            p.box[i] = (const float*)d_in[3 * i + 1];
            p.ctr[i] = (const float*)d_in[3 * i + 2];
        }
    } else {
        for (int i = 0; i < 5; i++) {          // planar cls x5, box x5, ctr x5
            p.cls[i] = (const float*)d_in[i];
            p.box[i] = (const float*)d_in[5 + i];
            p.ctr[i] = (const float*)d_in[10 + i];
        }
    }

    const int smem_bytes = CAP * 16 + 4096 + CAP * 4 + CAP * 4 + CAP + CAP
                         + NCLS * CLSCAP * 2 + SVCAP * 2;   // 129,024 B
    cudaFuncSetAttribute(select_nms_kernel,
                         cudaFuncAttributeMaxDynamicSharedMemorySize, smem_bytes);

    dim3 dgrid((NGROUP + 255) / 256, BATCH);
    decode_kernel<<<dgrid, 256>>>(p);

    select_nms_kernel<<<BATCH, NT2, smem_bytes>>>(p, (float*)d_out);
}